// round 6
// baseline (speedup 1.0000x reference)
#include <cuda_runtime.h>
#include <cstdint>

typedef uint32_t u32; typedef uint64_t u64;

#define Bb 8
#define Mm 2048
#define NNs 2048
#define Dd 128
#define BM 128
#define BN 64
#define TPB 256
#define NT 32

#define C2 0.7213475204444817f   /* 0.5 * log2(e) */
#define INV_KEEP 1.25f

// ---- pre-split bf16 copies of x1/x2 (hi/lo), packed u32 pairs, linear layout ----
__device__ u32 gQH[Bb*Mm*Dd/2], gQL[Bb*Mm*Dd/2];
__device__ u32 gKH[Bb*NNs*Dd/2], gKL[Bb*NNs*Dd/2];

// ---- smem layout: 256B-row bf16 tiles ----
#define OF_QH  0        /* 128x128 bf16 = 32KB */
#define OF_QL  32768
#define OF_K0  65536    /* buf0: KH 16KB + KL 16KB */
#define OF_K1  98304    /* buf1 */
#define SMEM_TOTAL 131072

__device__ __forceinline__ u32 swa(u32 base, int row, int colb){
    return base + (u32)(row * 256) + (u32)((((colb >> 4) ^ (row & 7)) << 4) + (colb & 15));
}
__device__ __forceinline__ void ldsm4(u32* r, u32 a){
    asm volatile("ldmatrix.sync.aligned.m8n8.x4.shared.b16 {%0,%1,%2,%3},[%4];"
        : "=r"(r[0]),"=r"(r[1]),"=r"(r[2]),"=r"(r[3]) : "r"(a));
}
__device__ __forceinline__ void ldsm4t(u32* r, u32 a){
    asm volatile("ldmatrix.sync.aligned.m8n8.x4.trans.shared.b16 {%0,%1,%2,%3},[%4];"
        : "=r"(r[0]),"=r"(r[1]),"=r"(r[2]),"=r"(r[3]) : "r"(a));
}
__device__ __forceinline__ void mmabf(float* c, const u32* a, u32 b0, u32 b1){
    asm volatile("mma.sync.aligned.m16n8k16.row.col.f32.bf16.bf16.f32 "
        "{%0,%1,%2,%3},{%4,%5,%6,%7},{%8,%9},{%0,%1,%2,%3};"
        : "+f"(c[0]),"+f"(c[1]),"+f"(c[2]),"+f"(c[3])
        : "r"(a[0]),"r"(a[1]),"r"(a[2]),"r"(a[3]),"r"(b0),"r"(b1));
}
__device__ __forceinline__ void split_pair(float p0, float p1, u32& h2, u32& l2){
    asm("cvt.rn.bf16x2.f32 %0, %1, %2;" : "=r"(h2) : "f"(p1), "f"(p0));
    float h0 = __uint_as_float(h2 << 16);
    float h1 = __uint_as_float(h2 & 0xffff0000u);
    float r0 = p0 - h0, r1 = p1 - h1;
    asm("cvt.rn.bf16x2.f32 %0, %1, %2;" : "=r"(l2) : "f"(r1), "f"(r0));
}
__device__ __forceinline__ float ex2f(float x){
    float r; asm("ex2.approx.f32 %0, %1;" : "=f"(r) : "f"(x)); return r;
}

// JAX threefry2x32 partitionable, bit-exact (frozen since R1).
__device__ __forceinline__ u32 tf_keep(u32 ctr)
{
    const u32 K1 = 42u;
    const u32 K2 = 0x1BD11BDAu ^ 42u;
    u32 x0 = 0u;
    u32 x1 = ctr + K1;
#define TF_RND(r) { x0 += x1; x1 = __funnelshift_l(x1, x1, (r)); x1 ^= x0; }
    TF_RND(13) TF_RND(15) TF_RND(26) TF_RND(6)
    x0 += K1; x1 += K2 + 1u;
    TF_RND(17) TF_RND(29) TF_RND(16) TF_RND(24)
    x0 += K2; x1 += 0u + 2u;
    TF_RND(13) TF_RND(15) TF_RND(26) TF_RND(6)
    x0 += 0u; x1 += K1 + 3u;
    TF_RND(17) TF_RND(29) TF_RND(16) TF_RND(24)
    x0 += K1; x1 += K2 + 4u;
    TF_RND(13) TF_RND(15) TF_RND(26) TF_RND(6)
    x0 += K2; x1 += 0u + 5u;
#undef TF_RND
    return (((x0 ^ x1) >> 9) <= 6710886u) ? 1u : 0u;
}

// ---------------------------------------------------------------------------
// Pre-pass: split fp32 x1/x2 into bf16 hi/lo device globals.
// 2^20 threads, each handles one float4 (4 floats -> 2 u32 hi + 2 u32 lo).
// ---------------------------------------------------------------------------
__global__ void __launch_bounds__(256)
split_prepass(const float* __restrict__ x1, const float* __restrict__ x2)
{
    int i = blockIdx.x * 256 + threadIdx.x;
    int half = i >> 19;              // 0: x1->Q, 1: x2->K
    int j = i & 0x7FFFF;             // float4 index within tensor
    const float4* src = (const float4*)(half ? x2 : x1);
    float4 v = src[j];
    u32 h0,l0,h1,l1;
    split_pair(v.x, v.y, h0, l0);
    split_pair(v.z, v.w, h1, l1);
    uint2* dh = (uint2*)(half ? gKH : gQH);
    uint2* dl = (uint2*)(half ? gKL : gQL);
    dh[j] = make_uint2(h0, h1);
    dl[j] = make_uint2(l0, l1);
}

// cp.async one 64-row bf16 K tile pair (hi+lo) into swizzled smem buffer
__device__ __forceinline__ void cp_k(u32 bufbase, int b, int n0, int tid){
    const char* srcH = (const char*)gKH;
    const char* srcL = (const char*)gKL;
    #pragma unroll
    for (int k = 0; k < 8; k++){
        int idx  = tid + k * TPB;           // 0..2047
        int half = idx >> 10;               // 0: hi, 1: lo
        int ci   = idx & 1023;
        int row  = ci >> 4;
        int c    = ci & 15;
        u32 da = bufbase + (u32)(half * 16384) + (u32)(row * 256) + (u32)((c ^ (row & 7)) << 4);
        const char* s = (half ? srcL : srcH) + ((size_t)(b * NNs + n0 + row) * 256 + c * 16);
        asm volatile("cp.async.cg.shared.global [%0], [%1], 16;" :: "r"(da), "l"(s));
    }
}

__global__ void __launch_bounds__(TPB, 1)
attn_hmma(const float* __restrict__ x1, const float* __restrict__ x2, float* __restrict__ out)
{
    extern __shared__ char sm[];
    const u32 smb = (u32)__cvta_generic_to_shared(sm);
    const int tid  = threadIdx.x;
    const int w    = tid >> 5;
    const int lane = tid & 31;
    const int gID  = lane >> 2;
    const int tig  = lane & 3;
    const int b    = blockIdx.y;
    const int mrow0 = blockIdx.x * BM;

    const u32 QH = smb + OF_QH, QL = smb + OF_QL;

    // ---- prologue: cp.async Q (full 128 rows, hi+lo) + K tile 0; one group ----
    {
        const char* srcH = (const char*)gQH;
        const char* srcL = (const char*)gQL;
        #pragma unroll
        for (int k = 0; k < 8; k++){
            int idx = tid + k * TPB;        // 0..2047 : Q hi chunks
            int row = idx >> 4, c = idx & 15;
            u32 da = QH + (u32)(row * 256) + (u32)((c ^ (row & 7)) << 4);
            const char* s = srcH + ((size_t)(b * Mm + mrow0 + row) * 256 + c * 16);
            asm volatile("cp.async.cg.shared.global [%0], [%1], 16;" :: "r"(da), "l"(s));
            u32 dl = QL + (u32)(row * 256) + (u32)((c ^ (row & 7)) << 4);
            const char* sl = srcL + ((size_t)(b * Mm + mrow0 + row) * 256 + c * 16);
            asm volatile("cp.async.cg.shared.global [%0], [%1], 16;" :: "r"(dl), "l"(sl));
        }
    }
    cp_k(smb + OF_K0, b, 0, tid);
    asm volatile("cp.async.commit_group;");

    const int r0  = w * 16;
    const int rA  = ((lane >> 3) & 1) * 8 + (lane & 7);
    const int cA  = ((lane >> 4) & 1) * 16;
    const int rBq = ((lane >> 4) & 1) * 8 + (lane & 7);
    const int cBq = ((lane >> 3) & 1) * 16;

    // ---- masks for tile 0 (overlaps the prologue copies) ----
    const u32 mbase = ((u32)(b * Mm + mrow0 + r0 + gID)) * 2048u + (u32)(2 * tig);
    u32 km0, km1;
    {
        u32 a0 = 0, a1 = 0;
        #pragma unroll 2
        for (int jj = 0; jj < 8; jj++){
            u32 c0 = mbase + (u32)(jj * 8);
            u32 c1 = c0 + 8u * 2048u;
            a0 |= (tf_keep(c0) << (2*jj)) | (tf_keep(c0 + 1u) << (2*jj + 1));
            a1 |= (tf_keep(c1) << (2*jj)) | (tf_keep(c1 + 1u) << (2*jj + 1));
        }
        km0 = a0; km1 = a1;
    }

    float o[16][4];
    #pragma unroll
    for (int i = 0; i < 16; i++){ o[i][0]=o[i][1]=o[i][2]=o[i][3]=0.f; }
    float lsum0 = 0.f, lsum1 = 0.f;

    asm volatile("cp.async.wait_group 0;" ::: "memory");
    __syncthreads();

    for (int t = 0; t < NT; t++){
        const u32 KB = smb + ((t & 1) ? OF_K1 : OF_K0);   // KH at +0, KL at +16384
        const u32 KH = KB, KL = KB + 16384;

        // prefetch next tile (buffer freed by last iteration's barrier)
        if (t < NT - 1){
            cp_k(smb + (((t + 1) & 1) ? OF_K1 : OF_K0), b, (t + 1) * BN, tid);
            asm volatile("cp.async.commit_group;");
        }

        // ---- QK: S(16x64) = Qh*Kh + Qh*Kl + Ql*Kh ----
        float s[8][4];
        #pragma unroll
        for (int i = 0; i < 8; i++){ s[i][0]=s[i][1]=s[i][2]=s[i][3]=0.f; }

        #pragma unroll
        for (int k = 0; k < 8; k++){
            int dby = k * 32;
            u32 ah[4], al[4];
            ldsm4(ah, swa(QH, rA + r0, dby + cA));
            ldsm4(al, swa(QL, rA + r0, dby + cA));
            #pragma unroll
            for (int nb = 0; nb < 4; nb++){
                u32 bh[4], bl[4];
                ldsm4(bh, swa(KH, nb * 16 + rBq, dby + cBq));
                ldsm4(bl, swa(KL, nb * 16 + rBq, dby + cBq));
                mmabf(s[2*nb],   ah, bh[0], bh[1]);
                mmabf(s[2*nb],   ah, bl[0], bl[1]);
                mmabf(s[2*nb],   al, bh[0], bh[1]);
                mmabf(s[2*nb+1], ah, bh[2], bh[3]);
                mmabf(s[2*nb+1], ah, bl[2], bl[3]);
                mmabf(s[2*nb+1], al, bh[2], bh[3]);
            }
        }

        // ---- softmax + dropout -> P fragments in registers ----
        u32 ph[4][4], pl[4][4];
        #pragma unroll
        for (int nb = 0; nb < 4; nb++){
            #pragma unroll
            for (int ng = 0; ng < 2; ng++){
                float* c = s[2*nb + ng];
                float p0 = ex2f(c[0] * C2);
                float p1 = ex2f(c[1] * C2);
                float p2 = ex2f(c[2] * C2);
                float p3 = ex2f(c[3] * C2);
                lsum0 += p0 + p1;
                lsum1 += p2 + p3;
                int jj = nb * 2 + ng;
                float q0 = ((km0 >> (2*jj)) & 1u)   ? p0 * INV_KEEP : 0.f;
                float q1 = ((km0 >> (2*jj+1)) & 1u) ? p1 * INV_KEEP : 0.f;
                float q2 = ((km1 >> (2*jj)) & 1u)   ? p2 * INV_KEEP : 0.f;
                float q3 = ((km1 >> (2*jj+1)) & 1u) ? p3 * INV_KEEP : 0.f;
                u32 h01, l01, h23, l23;
                split_pair(q0, q1, h01, l01);
                split_pair(q2, q3, h23, l23);
                ph[nb][2*ng]   = h01;  pl[nb][2*ng]   = l01;
                ph[nb][2*ng+1] = h23;  pl[nb][2*ng+1] = l23;
            }
        }

        // ---- masks for tile t+1: pure-alu stream, interleaves with PV below ----
        u32 nk0 = 0, nk1 = 0;
        if (t < NT - 1){
            u32 tb = mbase + (u32)((t + 1) * 64);
            #pragma unroll 2
            for (int jj = 0; jj < 8; jj++){
                u32 c0 = tb + (u32)(jj * 8);
                u32 c1 = c0 + 8u * 2048u;
                nk0 |= (tf_keep(c0) << (2*jj)) | (tf_keep(c0 + 1u) << (2*jj + 1));
                nk1 |= (tf_keep(c1) << (2*jj)) | (tf_keep(c1 + 1u) << (2*jj + 1));
            }
        }

        // ---- PV: O(16x128) += Ph*Vh + Ph*Vl + Pl*Vh  (V = K tile, trans) ----
        #pragma unroll
        for (int kk = 0; kk < 4; kk++){
            int n0 = kk * 16;
            #pragma unroll
            for (int dg = 0; dg < 8; dg++){
                int dby = dg * 32;
                u32 bh[4], bl[4];
                ldsm4t(bh, swa(KH, n0 + rA, dby + cA));
                ldsm4t(bl, swa(KL, n0 + rA, dby + cA));
                mmabf(o[2*dg],   ph[kk], bh[0], bh[1]);
                mmabf(o[2*dg],   ph[kk], bl[0], bl[1]);
                mmabf(o[2*dg],   pl[kk], bh[0], bh[1]);
                mmabf(o[2*dg+1], ph[kk], bh[2], bh[3]);
                mmabf(o[2*dg+1], ph[kk], bl[2], bl[3]);
                mmabf(o[2*dg+1], pl[kk], bh[2], bh[3]);
            }
        }

        km0 = nk0; km1 = nk1;

        if (t < NT - 1){
            asm volatile("cp.async.wait_group 0;" ::: "memory");
            __syncthreads();   // next buffer ready; all warps done with this one
        }
    }

    // ---- epilogue ----
    lsum0 += __shfl_xor_sync(0xffffffffu, lsum0, 1);
    lsum0 += __shfl_xor_sync(0xffffffffu, lsum0, 2);
    lsum1 += __shfl_xor_sync(0xffffffffu, lsum1, 1);
    lsum1 += __shfl_xor_sync(0xffffffffu, lsum1, 2);
    float inv0 = 1.0f / lsum0;
    float inv1 = 1.0f / lsum1;

    float* g0 = out + ((size_t)b * Mm + mrow0 + r0 + gID) * Dd;
    float* g1 = g0 + 8 * Dd;
    #pragma unroll
    for (int i = 0; i < 16; i++){
        int d = i * 8 + 2 * tig;
        *(float2*)(g0 + d) = make_float2(o[i][0] * inv0, o[i][1] * inv0);
        *(float2*)(g1 + d) = make_float2(o[i][2] * inv1, o[i][3] * inv1);
    }
}

extern "C" void kernel_launch(void* const* d_in, const int* in_sizes, int n_in,
                              void* d_out, int out_size)
{
    const float* x1 = (const float*)d_in[0];
    const float* x2 = (const float*)d_in[1];
    float* out = (float*)d_out;

    split_prepass<<<4096, 256>>>(x1, x2);

    cudaFuncSetAttribute(attn_hmma, cudaFuncAttributeMaxDynamicSharedMemorySize, SMEM_TOTAL);
    dim3 grid(Mm / BM, Bb);
    attn_hmma<<<grid, TPB, SMEM_TOTAL>>>(x1, x2, out);
}

// round 7
// speedup vs baseline: 1.0573x; 1.0573x over previous
#include <cuda_runtime.h>
#include <cstdint>

typedef uint32_t u32;

#define Bb 8
#define Mm 2048
#define NNs 2048
#define Dd 128
#define BM 128
#define BN 64
#define TPB 512
#define NT 32

#define C2 0.7213475204444817f   /* 0.5 * log2(e) */
#define INV_KEEP 1.25f

// pre-split bf16 copies of x1/x2 (hi/lo), packed u32 pairs, linear layout
__device__ u32 gQH[Bb*Mm*Dd/2], gQL[Bb*Mm*Dd/2];
__device__ u32 gKH[Bb*NNs*Dd/2], gKL[Bb*NNs*Dd/2];

// ---- smem byte offsets ----
#define OF_QH  0        /* 128x128 bf16 = 32KB */
#define OF_QL  32768
#define OF_K0  65536    /* KH 16KB + KL 16KB */
#define OF_K1  98304
#define OF_PH  131072   /* P hi: 128 x 64 bf16 = 16KB (128B rows) */
#define OF_PL  147456
#define OF_RED 163840   /* 256 floats */
#define SMEM_TOTAL 164864

// 256B-row tile swizzle (Q/K)
__device__ __forceinline__ u32 swa(u32 base, int row, int colb){
    return base + (u32)(row * 256) + (u32)((((colb >> 4) ^ (row & 7)) << 4) + (colb & 15));
}
// 128B-row tile swizzle (P)
__device__ __forceinline__ u32 swp(u32 base, int row, int colb){
    return base + (u32)(row * 128) + (u32)(((((colb >> 4) ^ (row & 7)) & 7) << 4) + (colb & 15));
}
__device__ __forceinline__ void ldsm4(u32* r, u32 a){
    asm volatile("ldmatrix.sync.aligned.m8n8.x4.shared.b16 {%0,%1,%2,%3},[%4];"
        : "=r"(r[0]),"=r"(r[1]),"=r"(r[2]),"=r"(r[3]) : "r"(a));
}
__device__ __forceinline__ void ldsm4t(u32* r, u32 a){
    asm volatile("ldmatrix.sync.aligned.m8n8.x4.trans.shared.b16 {%0,%1,%2,%3},[%4];"
        : "=r"(r[0]),"=r"(r[1]),"=r"(r[2]),"=r"(r[3]) : "r"(a));
}
__device__ __forceinline__ void mmabf(float* c, const u32* a, u32 b0, u32 b1){
    asm volatile("mma.sync.aligned.m16n8k16.row.col.f32.bf16.bf16.f32 "
        "{%0,%1,%2,%3},{%4,%5,%6,%7},{%8,%9},{%0,%1,%2,%3};"
        : "+f"(c[0]),"+f"(c[1]),"+f"(c[2]),"+f"(c[3])
        : "r"(a[0]),"r"(a[1]),"r"(a[2]),"r"(a[3]),"r"(b0),"r"(b1));
}
__device__ __forceinline__ void split_pair(float p0, float p1, u32& h2, u32& l2){
    asm("cvt.rn.bf16x2.f32 %0, %1, %2;" : "=r"(h2) : "f"(p1), "f"(p0));
    float h0 = __uint_as_float(h2 << 16);
    float h1 = __uint_as_float(h2 & 0xffff0000u);
    float r0 = p0 - h0, r1 = p1 - h1;
    asm("cvt.rn.bf16x2.f32 %0, %1, %2;" : "=r"(l2) : "f"(r1), "f"(r0));
}
__device__ __forceinline__ float ex2f(float x){
    float r; asm("ex2.approx.f32 %0, %1;" : "=f"(r) : "f"(x)); return r;
}

// JAX threefry2x32 partitionable, bit-exact (frozen since R1).
__device__ __forceinline__ u32 tf_keep(u32 ctr)
{
    const u32 K1 = 42u;
    const u32 K2 = 0x1BD11BDAu ^ 42u;
    u32 x0 = 0u;
    u32 x1 = ctr + K1;
#define TF_RND(r) { x0 += x1; x1 = __funnelshift_l(x1, x1, (r)); x1 ^= x0; }
    TF_RND(13) TF_RND(15) TF_RND(26) TF_RND(6)
    x0 += K1; x1 += K2 + 1u;
    TF_RND(17) TF_RND(29) TF_RND(16) TF_RND(24)
    x0 += K2; x1 += 0u + 2u;
    TF_RND(13) TF_RND(15) TF_RND(26) TF_RND(6)
    x0 += 0u; x1 += K1 + 3u;
    TF_RND(17) TF_RND(29) TF_RND(16) TF_RND(24)
    x0 += K1; x1 += K2 + 4u;
    TF_RND(13) TF_RND(15) TF_RND(26) TF_RND(6)
    x0 += K2; x1 += 0u + 5u;
#undef TF_RND
    return (((x0 ^ x1) >> 9) <= 6710886u) ? 1u : 0u;
}

__global__ void __launch_bounds__(256)
split_prepass(const float* __restrict__ x1, const float* __restrict__ x2)
{
    int i = blockIdx.x * 256 + threadIdx.x;
    int half = i >> 19;
    int j = i & 0x7FFFF;
    const float4* src = (const float4*)(half ? x2 : x1);
    float4 v = src[j];
    u32 h0,l0,h1,l1;
    split_pair(v.x, v.y, h0, l0);
    split_pair(v.z, v.w, h1, l1);
    uint2* dh = (uint2*)(half ? gKH : gQH);
    uint2* dl = (uint2*)(half ? gKL : gQL);
    dh[j] = make_uint2(h0, h1);
    dl[j] = make_uint2(l0, l1);
}

// cp.async one 64-row bf16 K tile pair (hi+lo) into swizzled smem buffer
__device__ __forceinline__ void cp_k(u32 bufbase, int b, int n0, int tid){
    #pragma unroll
    for (int k = 0; k < 4; k++){
        int idx  = tid + k * TPB;           // 0..2047
        int half = idx >> 10;
        int ci   = idx & 1023;
        int row  = ci >> 4;
        int c    = ci & 15;
        u32 da = bufbase + (u32)(half * 16384) + (u32)(row * 256) + (u32)((c ^ (row & 7)) << 4);
        const char* s = (const char*)(half ? gKL : gKH)
                      + ((size_t)(b * NNs + n0 + row) * 256 + c * 16);
        asm volatile("cp.async.cg.shared.global [%0], [%1], 16;" :: "r"(da), "l"(s));
    }
}

__global__ void __launch_bounds__(TPB, 1)
attn_hmma(const float* __restrict__ x1, const float* __restrict__ x2, float* __restrict__ out)
{
    extern __shared__ char sm[];
    const u32 smb = (u32)__cvta_generic_to_shared(sm);
    const int tid  = threadIdx.x;
    const int w    = tid >> 5;
    const int lane = tid & 31;
    const int gID  = lane >> 2;
    const int tig  = lane & 3;
    const int g    = w >> 1;          // row group: rows 16g..16g+15
    const int s    = w & 1;           // col half: QK n 32s.., PV d 64s..
    const int b    = blockIdx.y;
    const int mrow0 = blockIdx.x * BM;

    const u32 QH = smb + OF_QH, QL = smb + OF_QL;
    const u32 PH = smb + OF_PH, PL = smb + OF_PL;

    // ---- prologue: Q (hi+lo) + K tile 0 ----
    #pragma unroll
    for (int k = 0; k < 8; k++){
        int idx = tid + k * TPB;        // 0..4095
        int half = idx >> 11;
        int ci = idx & 2047;
        int row = ci >> 4, c = ci & 15;
        u32 da = (half ? QL : QH) + (u32)(row * 256) + (u32)((c ^ (row & 7)) << 4);
        const char* src = (const char*)(half ? gQL : gQH)
                        + ((size_t)(b * Mm + mrow0 + row) * 256 + c * 16);
        asm volatile("cp.async.cg.shared.global [%0], [%1], 16;" :: "r"(da), "l"(src));
    }
    cp_k(smb + OF_K0, b, 0, tid);
    asm volatile("cp.async.commit_group;");

    const int rA  = ((lane >> 3) & 1) * 8 + (lane & 7);
    const int cA  = ((lane >> 4) & 1) * 16;
    const int rBq = ((lane >> 4) & 1) * 8 + (lane & 7);
    const int cBq = ((lane >> 3) & 1) * 16;

    const u32 mrow = ((u32)(b * Mm + mrow0 + 16 * g + gID)) * 2048u;
    const u32 mcol0 = (u32)(32 * s + 2 * tig);

    float o[8][4];
    #pragma unroll
    for (int i = 0; i < 8; i++){ o[i][0]=o[i][1]=o[i][2]=o[i][3]=0.f; }
    float lsum0 = 0.f, lsum1 = 0.f;

    asm volatile("cp.async.wait_group 0;" ::: "memory");
    __syncthreads();

    for (int t = 0; t < NT; t++){
        const u32 KB = smb + ((t & 1) ? OF_K1 : OF_K0);
        const u32 KHt = KB, KLt = KB + 16384;

        if (t < NT - 1){
            cp_k(smb + (((t + 1) & 1) ? OF_K1 : OF_K0), b, (t + 1) * BN, tid);
            asm volatile("cp.async.commit_group;");
        }

        // ---- dropout masks for tile t (8 bits per row-line) ----
        u32 km0 = 0, km1 = 0;
        {
            u32 c0 = mrow + (u32)(t * 64) + mcol0;
            u32 c1 = c0 + 8u * 2048u;
            #pragma unroll 2
            for (int nb = 0; nb < 4; nb++){
                u32 a = c0 + (u32)(8 * nb);
                u32 bcl = c1 + (u32)(8 * nb);
                km0 |= (tf_keep(a) << (2*nb)) | (tf_keep(a + 1u) << (2*nb + 1));
                km1 |= (tf_keep(bcl) << (2*nb)) | (tf_keep(bcl + 1u) << (2*nb + 1));
            }
        }

        // ---- QK: S(16x32) = Qh*Kh + Qh*Kl + Ql*Kh ----
        float s4[4][4];
        #pragma unroll
        for (int i = 0; i < 4; i++){ s4[i][0]=s4[i][1]=s4[i][2]=s4[i][3]=0.f; }

        #pragma unroll
        for (int k = 0; k < 8; k++){
            int dby = k * 32;
            u32 ah[4], al[4];
            ldsm4(ah, swa(QH, 16 * g + rA, dby + cA));
            ldsm4(al, swa(QL, 16 * g + rA, dby + cA));
            #pragma unroll
            for (int nb = 0; nb < 2; nb++){
                u32 bh[4], bl[4];
                ldsm4(bh, swa(KHt, 32 * s + nb * 16 + rBq, dby + cBq));
                ldsm4(bl, swa(KLt, 32 * s + nb * 16 + rBq, dby + cBq));
                mmabf(s4[2*nb],   ah, bh[0], bh[1]);
                mmabf(s4[2*nb],   ah, bl[0], bl[1]);
                mmabf(s4[2*nb],   al, bh[0], bh[1]);
                mmabf(s4[2*nb+1], ah, bh[2], bh[3]);
                mmabf(s4[2*nb+1], ah, bl[2], bl[3]);
                mmabf(s4[2*nb+1], al, bh[2], bh[3]);
            }
        }

        // ---- softmax + dropout -> P (hi/lo) into smem ----
        #pragma unroll
        for (int nb = 0; nb < 4; nb++){
            float* c = s4[nb];
            float p0 = ex2f(c[0] * C2);
            float p1 = ex2f(c[1] * C2);
            float p2 = ex2f(c[2] * C2);
            float p3 = ex2f(c[3] * C2);
            lsum0 += p0 + p1;
            lsum1 += p2 + p3;
            float q0 = ((km0 >> (2*nb)) & 1u)   ? p0 * INV_KEEP : 0.f;
            float q1 = ((km0 >> (2*nb+1)) & 1u) ? p1 * INV_KEEP : 0.f;
            float q2 = ((km1 >> (2*nb)) & 1u)   ? p2 * INV_KEEP : 0.f;
            float q3 = ((km1 >> (2*nb+1)) & 1u) ? p3 * INV_KEEP : 0.f;
            u32 h01, l01, h23, l23;
            split_pair(q0, q1, h01, l01);
            split_pair(q2, q3, h23, l23);
            int colb = 64 * s + 16 * nb + 4 * tig;
            int r0 = 16 * g + gID;
            *(u32*)(sm + OF_PH - 0 + 0) ;  // (no-op placeholder removed by compiler)
            *(u32*)(sm + (swp(0, r0,     colb) + OF_PH)) = h01;
            *(u32*)(sm + (swp(0, r0 + 8, colb) + OF_PH)) = h23;
            *(u32*)(sm + (swp(0, r0,     colb) + OF_PL)) = l01;
            *(u32*)(sm + (swp(0, r0 + 8, colb) + OF_PL)) = l23;
        }
        __syncthreads();   // P visible to partner warps

        // ---- PV: O(16x64) += Ph*Vh + Ph*Vl + Pl*Vh  (V = K tile, trans) ----
        #pragma unroll
        for (int kk = 0; kk < 4; kk++){
            u32 pA[4], pB[4];
            ldsm4(pA, swp(PH, 16 * g + rA, 32 * kk + cA));
            ldsm4(pB, swp(PL, 16 * g + rA, 32 * kk + cA));
            #pragma unroll
            for (int dgp = 0; dgp < 4; dgp++){
                int colb = 128 * s + 32 * dgp + cA;
                u32 bh[4], bl[4];
                ldsm4t(bh, swa(KHt, 16 * kk + rA, colb));
                ldsm4t(bl, swa(KLt, 16 * kk + rA, colb));
                mmabf(o[2*dgp],   pA, bh[0], bh[1]);
                mmabf(o[2*dgp],   pA, bl[0], bl[1]);
                mmabf(o[2*dgp],   pB, bh[0], bh[1]);
                mmabf(o[2*dgp+1], pA, bh[2], bh[3]);
                mmabf(o[2*dgp+1], pA, bl[2], bl[3]);
                mmabf(o[2*dgp+1], pB, bh[2], bh[3]);
            }
        }

        if (t < NT - 1){
            asm volatile("cp.async.wait_group 0;" ::: "memory");
        }
        __syncthreads();   // P & K buffers free for next tile
    }

    // ---- epilogue: cross-half row sums via smem, then write O/l ----
    lsum0 += __shfl_xor_sync(0xffffffffu, lsum0, 1);
    lsum0 += __shfl_xor_sync(0xffffffffu, lsum0, 2);
    lsum1 += __shfl_xor_sync(0xffffffffu, lsum1, 1);
    lsum1 += __shfl_xor_sync(0xffffffffu, lsum1, 2);
    float* red = (float*)(sm + OF_RED);
    if (tig == 0){
        red[(16 * g + gID) * 2 + s]     = lsum0;
        red[(16 * g + gID + 8) * 2 + s] = lsum1;
    }
    __syncthreads();
    int r0 = 16 * g + gID;
    float inv0 = 1.0f / (red[r0 * 2] + red[r0 * 2 + 1]);
    float inv1 = 1.0f / (red[(r0 + 8) * 2] + red[(r0 + 8) * 2 + 1]);

    float* g0 = out + ((size_t)b * Mm + mrow0 + r0) * Dd + 64 * s;
    float* g1 = g0 + 8 * Dd;
    #pragma unroll
    for (int db = 0; db < 8; db++){
        int d = db * 8 + 2 * tig;
        *(float2*)(g0 + d) = make_float2(o[db][0] * inv0, o[db][1] * inv0);
        *(float2*)(g1 + d) = make_float2(o[db][2] * inv1, o[db][3] * inv1);
    }
}

extern "C" void kernel_launch(void* const* d_in, const int* in_sizes, int n_in,
                              void* d_out, int out_size)
{
    const float* x1 = (const float*)d_in[0];
    const float* x2 = (const float*)d_in[1];
    float* out = (float*)d_out;

    split_prepass<<<4096, 256>>>(x1, x2);

    cudaFuncSetAttribute(attn_hmma, cudaFuncAttributeMaxDynamicSharedMemorySize, SMEM_TOTAL);
    dim3 grid(Mm / BM, Bb);
    attn_hmma<<<grid, TPB, SMEM_TOTAL>>>(x1, x2, out);
}

// round 8
// speedup vs baseline: 1.1692x; 1.1058x over previous
#include <cuda_runtime.h>
#include <cstdint>

typedef uint32_t u32;

#define Bb 8
#define Mm 2048
#define NNs 2048
#define Dd 128
#define BM 128
#define BN 64
#define TPB 640
#define NCT 512          /* compute threads (warps 0-15) */
#define NT 32

#define C2 0.7213475204444817f   /* 0.5 * log2(e) */
#define INV_KEEP 1.25f

// pre-split bf16 copies of x1/x2 (hi/lo), packed u32 pairs, linear layout
__device__ u32 gQH[Bb*Mm*Dd/2], gQL[Bb*Mm*Dd/2];
__device__ u32 gKH[Bb*NNs*Dd/2], gKL[Bb*NNs*Dd/2];

// ---- smem byte offsets ----
#define OF_QH  0        /* 128x128 bf16 = 32KB */
#define OF_QL  32768
#define OF_K0  65536    /* KH 16KB + KL 16KB */
#define OF_K1  98304
#define OF_PH  131072   /* P hi: 128 x 64 bf16 = 16KB (128B rows) */
#define OF_PL  147456
#define OF_MK  163840   /* 2 x 128 x 2 u32 keep-bit buffers = 2KB */
#define OF_RED 165888   /* 256 floats */
#define SMEM_TOTAL 166912

__device__ __forceinline__ u32 swa(u32 base, int row, int colb){
    return base + (u32)(row * 256) + (u32)((((colb >> 4) ^ (row & 7)) << 4) + (colb & 15));
}
__device__ __forceinline__ u32 swp(u32 base, int row, int colb){
    return base + (u32)(row * 128) + (u32)(((((colb >> 4) ^ (row & 7)) & 7) << 4) + (colb & 15));
}
__device__ __forceinline__ void ldsm4(u32* r, u32 a){
    asm volatile("ldmatrix.sync.aligned.m8n8.x4.shared.b16 {%0,%1,%2,%3},[%4];"
        : "=r"(r[0]),"=r"(r[1]),"=r"(r[2]),"=r"(r[3]) : "r"(a));
}
__device__ __forceinline__ void ldsm4t(u32* r, u32 a){
    asm volatile("ldmatrix.sync.aligned.m8n8.x4.trans.shared.b16 {%0,%1,%2,%3},[%4];"
        : "=r"(r[0]),"=r"(r[1]),"=r"(r[2]),"=r"(r[3]) : "r"(a));
}
__device__ __forceinline__ void mmabf(float* c, const u32* a, u32 b0, u32 b1){
    asm volatile("mma.sync.aligned.m16n8k16.row.col.f32.bf16.bf16.f32 "
        "{%0,%1,%2,%3},{%4,%5,%6,%7},{%8,%9},{%0,%1,%2,%3};"
        : "+f"(c[0]),"+f"(c[1]),"+f"(c[2]),"+f"(c[3])
        : "r"(a[0]),"r"(a[1]),"r"(a[2]),"r"(a[3]),"r"(b0),"r"(b1));
}
__device__ __forceinline__ void split_pair(float p0, float p1, u32& h2, u32& l2){
    asm("cvt.rn.bf16x2.f32 %0, %1, %2;" : "=r"(h2) : "f"(p1), "f"(p0));
    float h0 = __uint_as_float(h2 << 16);
    float h1 = __uint_as_float(h2 & 0xffff0000u);
    float r0 = p0 - h0, r1 = p1 - h1;
    asm("cvt.rn.bf16x2.f32 %0, %1, %2;" : "=r"(l2) : "f"(r1), "f"(r0));
}
__device__ __forceinline__ float ex2f(float x){
    float r; asm("ex2.approx.f32 %0, %1;" : "=f"(r) : "f"(x)); return r;
}

// JAX threefry2x32 partitionable, bit-exact (frozen since R1).
__device__ __forceinline__ u32 tf_keep(u32 ctr)
{
    const u32 K1 = 42u;
    const u32 K2 = 0x1BD11BDAu ^ 42u;
    u32 x0 = 0u;
    u32 x1 = ctr + K1;
#define TF_RND(r) { x0 += x1; x1 = __funnelshift_l(x1, x1, (r)); x1 ^= x0; }
    TF_RND(13) TF_RND(15) TF_RND(26) TF_RND(6)
    x0 += K1; x1 += K2 + 1u;
    TF_RND(17) TF_RND(29) TF_RND(16) TF_RND(24)
    x0 += K2; x1 += 0u + 2u;
    TF_RND(13) TF_RND(15) TF_RND(26) TF_RND(6)
    x0 += 0u; x1 += K1 + 3u;
    TF_RND(17) TF_RND(29) TF_RND(16) TF_RND(24)
    x0 += K1; x1 += K2 + 4u;
    TF_RND(13) TF_RND(15) TF_RND(26) TF_RND(6)
    x0 += K2; x1 += 0u + 5u;
#undef TF_RND
    return (((x0 ^ x1) >> 9) <= 6710886u) ? 1u : 0u;
}

__global__ void __launch_bounds__(256)
split_prepass(const float* __restrict__ x1, const float* __restrict__ x2)
{
    int i = blockIdx.x * 256 + threadIdx.x;
    int half = i >> 19;
    int j = i & 0x7FFFF;
    const float4* src = (const float4*)(half ? x2 : x1);
    float4 v = src[j];
    u32 h0,l0,h1,l1;
    split_pair(v.x, v.y, h0, l0);
    split_pair(v.z, v.w, h1, l1);
    uint2* dh = (uint2*)(half ? gKH : gQH);
    uint2* dl = (uint2*)(half ? gKL : gQL);
    dh[j] = make_uint2(h0, h1);
    dl[j] = make_uint2(l0, l1);
}

// cp.async one 64-row bf16 K tile pair (hi+lo); 512 threads, 4 chunks each
__device__ __forceinline__ void cp_k(u32 bufbase, int b, int n0, int tid){
    #pragma unroll
    for (int k = 0; k < 4; k++){
        int idx  = tid + k * NCT;           // 0..2047
        int half = idx >> 10;
        int ci   = idx & 1023;
        int row  = ci >> 4;
        int c    = ci & 15;
        u32 da = bufbase + (u32)(half * 16384) + (u32)(row * 256) + (u32)((c ^ (row & 7)) << 4);
        const char* s = (const char*)(half ? gKL : gKH)
                      + ((size_t)(b * NNs + n0 + row) * 256 + c * 16);
        asm volatile("cp.async.cg.shared.global [%0], [%1], 16;" :: "r"(da), "l"(s));
    }
}

__global__ void __launch_bounds__(TPB, 1)
attn_hmma(const float* __restrict__ x1, const float* __restrict__ x2, float* __restrict__ out)
{
    extern __shared__ char sm[];
    const u32 smb = (u32)__cvta_generic_to_shared(sm);
    const int tid  = threadIdx.x;
    const int w    = tid >> 5;
    const int lane = tid & 31;
    const int gID  = lane >> 2;
    const int tig  = lane & 3;
    const int g    = w >> 1;          // compute: rows 16g..16g+15
    const int s    = w & 1;           // compute: col half
    const int b    = blockIdx.y;
    const int mrow0 = blockIdx.x * BM;

    const u32 QH = smb + OF_QH, QL = smb + OF_QL;
    const u32 PH = smb + OF_PH, PL = smb + OF_PL;

    // ---- prologue ----
    if (tid < NCT){
        #pragma unroll
        for (int k = 0; k < 8; k++){
            int idx = tid + k * NCT;        // 0..4095
            int half = idx >> 11;
            int ci = idx & 2047;
            int row = ci >> 4, c = ci & 15;
            u32 da = (half ? QL : QH) + (u32)(row * 256) + (u32)((c ^ (row & 7)) << 4);
            const char* src = (const char*)(half ? gQL : gQH)
                            + ((size_t)(b * Mm + mrow0 + row) * 256 + c * 16);
            asm volatile("cp.async.cg.shared.global [%0], [%1], 16;" :: "r"(da), "l"(src));
        }
        cp_k(smb + OF_K0, b, 0, tid);
        asm volatile("cp.async.commit_group;");
    } else {
        // mask warps: generate tile-0 keep bits into buffer 0
        int row = (w - 16) * 32 + lane;
        u32 base = ((u32)(b * Mm + mrow0 + row)) * 2048u;
        u32 m0 = 0, m1 = 0;
        #pragma unroll 4
        for (int j = 0; j < 32; j++){
            m0 |= tf_keep(base + (u32)j) << j;
            m1 |= tf_keep(base + 32u + (u32)j) << j;
        }
        u32* mk = (u32*)(sm + OF_MK);
        mk[row * 2]     = m0;
        mk[row * 2 + 1] = m1;
    }

    const int rA  = ((lane >> 3) & 1) * 8 + (lane & 7);
    const int cA  = ((lane >> 4) & 1) * 16;
    const int rBq = ((lane >> 4) & 1) * 8 + (lane & 7);
    const int cBq = ((lane >> 3) & 1) * 16;

    float o[8][4];
    #pragma unroll
    for (int i = 0; i < 8; i++){ o[i][0]=o[i][1]=o[i][2]=o[i][3]=0.f; }
    float lsum0 = 0.f, lsum1 = 0.f;

    if (tid < NCT){ asm volatile("cp.async.wait_group 0;" ::: "memory"); }
    __syncthreads();

    for (int t = 0; t < NT; t++){
        const u32 KB = smb + ((t & 1) ? OF_K1 : OF_K0);
        const u32 KHt = KB, KLt = KB + 16384;

        if (tid < NCT && t < NT - 1){
            cp_k(smb + (((t + 1) & 1) ? OF_K1 : OF_K0), b, (t + 1) * BN, tid);
            asm volatile("cp.async.commit_group;");
        }

        if (w < 16){
            // ---- QK: S(16x32) = Qh*Kh + Qh*Kl + Ql*Kh ----
            float s4[4][4];
            #pragma unroll
            for (int i = 0; i < 4; i++){ s4[i][0]=s4[i][1]=s4[i][2]=s4[i][3]=0.f; }

            #pragma unroll
            for (int k = 0; k < 8; k++){
                int dby = k * 32;
                u32 ah[4], al[4];
                ldsm4(ah, swa(QH, 16 * g + rA, dby + cA));
                ldsm4(al, swa(QL, 16 * g + rA, dby + cA));
                #pragma unroll
                for (int nb = 0; nb < 2; nb++){
                    u32 bh[4], bl[4];
                    ldsm4(bh, swa(KHt, 32 * s + nb * 16 + rBq, dby + cBq));
                    ldsm4(bl, swa(KLt, 32 * s + nb * 16 + rBq, dby + cBq));
                    mmabf(s4[2*nb],   ah, bh[0], bh[1]);
                    mmabf(s4[2*nb],   ah, bl[0], bl[1]);
                    mmabf(s4[2*nb],   al, bh[0], bh[1]);
                    mmabf(s4[2*nb+1], ah, bh[2], bh[3]);
                    mmabf(s4[2*nb+1], ah, bl[2], bl[3]);
                    mmabf(s4[2*nb+1], al, bh[2], bh[3]);
                }
            }

            // ---- softmax + dropout (mask bits from smem) -> P hi/lo ----
            const u32* mk = (const u32*)(sm + OF_MK + ((t & 1) ? 1024 : 0));
            int r0 = 16 * g + gID;
            u32 mw0 = mk[r0 * 2 + s];
            u32 mw1 = mk[(r0 + 8) * 2 + s];
            #pragma unroll
            for (int nb = 0; nb < 4; nb++){
                float* c = s4[nb];
                float p0 = ex2f(c[0] * C2);
                float p1 = ex2f(c[1] * C2);
                float p2 = ex2f(c[2] * C2);
                float p3 = ex2f(c[3] * C2);
                lsum0 += p0 + p1;
                lsum1 += p2 + p3;
                int bit = 8 * nb + 2 * tig;
                float q0 = ((mw0 >> bit) & 1u)       ? p0 * INV_KEEP : 0.f;
                float q1 = ((mw0 >> (bit + 1)) & 1u) ? p1 * INV_KEEP : 0.f;
                float q2 = ((mw1 >> bit) & 1u)       ? p2 * INV_KEEP : 0.f;
                float q3 = ((mw1 >> (bit + 1)) & 1u) ? p3 * INV_KEEP : 0.f;
                u32 h01, l01, h23, l23;
                split_pair(q0, q1, h01, l01);
                split_pair(q2, q3, h23, l23);
                int colb = 64 * s + 16 * nb + 4 * tig;
                *(u32*)(sm + swp(OF_PH, r0,     colb)) = h01;
                *(u32*)(sm + swp(OF_PH, r0 + 8, colb)) = h23;
                *(u32*)(sm + swp(OF_PL, r0,     colb)) = l01;
                *(u32*)(sm + swp(OF_PL, r0 + 8, colb)) = l23;
            }
            // compute-warp barrier: P visible across the 16 compute warps
            asm volatile("bar.sync 1, %0;" :: "n"(NCT) : "memory");

            // ---- PV: O(16x64) += Ph*Vh + Ph*Vl + Pl*Vh ----
            #pragma unroll
            for (int kk = 0; kk < 4; kk++){
                u32 pA[4], pB[4];
                ldsm4(pA, swp(PH, 16 * g + rA, 32 * kk + cA));
                ldsm4(pB, swp(PL, 16 * g + rA, 32 * kk + cA));
                #pragma unroll
                for (int dgp = 0; dgp < 4; dgp++){
                    int colb = 128 * s + 32 * dgp + cA;
                    u32 bh[4], bl[4];
                    ldsm4t(bh, swa(KHt, 16 * kk + rA, colb));
                    ldsm4t(bl, swa(KLt, 16 * kk + rA, colb));
                    mmabf(o[2*dgp],   pA, bh[0], bh[1]);
                    mmabf(o[2*dgp],   pA, bl[0], bl[1]);
                    mmabf(o[2*dgp],   pB, bh[0], bh[1]);
                    mmabf(o[2*dgp+1], pA, bh[2], bh[3]);
                    mmabf(o[2*dgp+1], pA, bl[2], bl[3]);
                    mmabf(o[2*dgp+1], pB, bh[2], bh[3]);
                }
            }
        } else if (t < NT - 1){
            // ---- mask warps: keep bits for tile t+1 ----
            int row = (w - 16) * 32 + lane;
            u32 base = ((u32)(b * Mm + mrow0 + row)) * 2048u + (u32)((t + 1) * 64);
            u32 m0 = 0, m1 = 0;
            #pragma unroll 4
            for (int j = 0; j < 32; j++){
                m0 |= tf_keep(base + (u32)j) << j;
                m1 |= tf_keep(base + 32u + (u32)j) << j;
            }
            u32* mk = (u32*)(sm + OF_MK + (((t + 1) & 1) ? 1024 : 0));
            mk[row * 2]     = m0;
            mk[row * 2 + 1] = m1;
        }

        if (tid < NCT && t < NT - 1){
            asm volatile("cp.async.wait_group 0;" ::: "memory");
        }
        __syncthreads();   // K/P/mask buffers handed off
    }

    // ---- epilogue ----
    float* red = (float*)(sm + OF_RED);
    if (w < 16){
        lsum0 += __shfl_xor_sync(0xffffffffu, lsum0, 1);
        lsum0 += __shfl_xor_sync(0xffffffffu, lsum0, 2);
        lsum1 += __shfl_xor_sync(0xffffffffu, lsum1, 1);
        lsum1 += __shfl_xor_sync(0xffffffffu, lsum1, 2);
        if (tig == 0){
            red[(16 * g + gID) * 2 + s]     = lsum0;
            red[(16 * g + gID + 8) * 2 + s] = lsum1;
        }
    }
    __syncthreads();
    if (w < 16){
        int r0 = 16 * g + gID;
        float inv0 = 1.0f / (red[r0 * 2] + red[r0 * 2 + 1]);
        float inv1 = 1.0f / (red[(r0 + 8) * 2] + red[(r0 + 8) * 2 + 1]);

        float* g0 = out + ((size_t)b * Mm + mrow0 + r0) * Dd + 64 * s;
        float* g1 = g0 + 8 * Dd;
        #pragma unroll
        for (int db = 0; db < 8; db++){
            int d = db * 8 + 2 * tig;
            *(float2*)(g0 + d) = make_float2(o[db][0] * inv0, o[db][1] * inv0);
            *(float2*)(g1 + d) = make_float2(o[db][2] * inv1, o[db][3] * inv1);
        }
    }
}

extern "C" void kernel_launch(void* const* d_in, const int* in_sizes, int n_in,
                              void* d_out, int out_size)
{
    const float* x1 = (const float*)d_in[0];
    const float* x2 = (const float*)d_in[1];
    float* out = (float*)d_out;

    split_prepass<<<4096, 256>>>(x1, x2);

    cudaFuncSetAttribute(attn_hmma, cudaFuncAttributeMaxDynamicSharedMemorySize, SMEM_TOTAL);
    dim3 grid(Mm / BM, Bb);
    attn_hmma<<<grid, TPB, SMEM_TOTAL>>>(x1, x2, out);
}